// round 12
// baseline (speedup 1.0000x reference)
#include <cuda_runtime.h>
#include <cuda_fp16.h>
#include <cstdint>

#define N_NODES 100000
#define N_EDGES 1600000
#define N_GRAPHS 1024
#define SCAN_BLOCKS ((N_NODES + 1023) / 1024)  // 98

// ---------------- scratch (static __device__; no allocation) ----------------
__device__ int    g_is64;
__device__ int    g_src[N_EDGES];
__device__ int    g_dst[N_EDGES];
__device__ int    g_cnt[N_NODES];
__device__ int    g_ptr[N_NODES + 1];
__device__ int    g_fill[N_NODES];
__device__ int    g_srcbuf[N_EDGES];
__device__ float  g_deginv[N_NODES];
__device__ int    g_gcnt[N_GRAPHS];
__device__ int    g_gptr[N_GRAPHS + 1];
__device__ int    g_bsum[SCAN_BLOCKS];
__device__ int    g_boff[SCAN_BLOCKS];
__device__ float  g_aggx[N_NODES * 64];                 // layer-1 aggregated x (fp32)
__device__ __half g_xh[(size_t)N_NODES * 64];           // fp16 x (layer-1 gather)
__device__ __half g_hh[(size_t)N_NODES * 128];          // fp16 activations (GEMM A source)
__device__ __half g_yh[(size_t)N_NODES * 64];           // fp16 gather half of y
__device__ float  g_ys[(size_t)N_NODES * 64];           // fp32 self half of y
__device__ float  g_pool[N_GRAPHS * 64];
__device__ __half g_bt1[128 * 128];                     // W^T fp16 per layer (Bt[n][k])
__device__ __half g_bt2[128 * 128];
__device__ __half g_bt3[128 * 64];
__device__ __half g_bt4[128 * 64];

__device__ __forceinline__ int clampN(int v, int n) {
    return ((unsigned)v < (unsigned)n) ? v : 0;
}

template <int B>
__device__ __forceinline__ const __half* btp() {
    if (B == 1) return g_bt1;
    if (B == 2) return g_bt2;
    if (B == 3) return g_bt3;
    return g_bt4;
}

__device__ __forceinline__ uint32_t s2u(const void* p) {
    uint32_t a;
    asm("{ .reg .u64 t; cvta.to.shared.u64 t, %1; cvt.u32.u64 %0, t; }" : "=r"(a) : "l"(p));
    return a;
}

__device__ __forceinline__ void ldsm_x4(uint32_t addr, uint32_t& r0, uint32_t& r1,
                                        uint32_t& r2, uint32_t& r3) {
    asm volatile("ldmatrix.sync.aligned.m8n8.x4.shared.b16 {%0,%1,%2,%3}, [%4];"
                 : "=r"(r0), "=r"(r1), "=r"(r2), "=r"(r3) : "r"(addr));
}

__device__ __forceinline__ void mma16816(float* d, const uint32_t* a,
                                         uint32_t b0, uint32_t b1) {
    asm volatile(
        "mma.sync.aligned.m16n8k16.row.col.f32.f16.f16.f32 "
        "{%0,%1,%2,%3}, {%4,%5,%6,%7}, {%8,%9}, {%0,%1,%2,%3};"
        : "+f"(d[0]), "+f"(d[1]), "+f"(d[2]), "+f"(d[3])
        : "r"(a[0]), "r"(a[1]), "r"(a[2]), "r"(a[3]), "r"(b0), "r"(b1));
}

// ---------------- zero + detect + weight-transpose prep (fused) ----------------
__global__ void k_zero(const unsigned int* __restrict__ ei_raw,
                       const float* __restrict__ w1l, const float* __restrict__ w1r,
                       const float* __restrict__ w2l, const float* __restrict__ w2r,
                       const float* __restrict__ w3l, const float* __restrict__ w3r,
                       const float* __restrict__ w4l, const float* __restrict__ w4r) {
    int i = blockIdx.x * blockDim.x + threadIdx.x;
    if (i < N_NODES) g_cnt[i] = 0;
    if (i < N_GRAPHS) g_gcnt[i] = 0;
    if (i == 0) {
        int is64 = 1;
        for (int t = 0; t < 128; t++) {
            if (ei_raw[2 * t + 1] != 0u) { is64 = 0; break; }
        }
        g_is64 = is64;
    }
    // Bt[n][k] = W[k][n] in fp16
    if (i < 16384) {
        int n = i >> 7, k = i & 127;
        float v = (k < 64) ? w1l[k * 128 + n] : w1r[(k - 64) * 128 + n];
        g_bt1[n * 128 + k] = __float2half(v);
    } else if (i < 32768) {
        int j = i - 16384, n = j >> 7, k = j & 127;
        float v = (n < 64) ? w2l[k * 64 + n] : w2r[k * 64 + (n - 64)];
        g_bt2[n * 128 + k] = __float2half(v);
    } else if (i < 40960) {
        int j = i - 32768, n = j >> 6, k = j & 63;
        float v = (n < 64) ? w3l[k * 64 + n] : w3r[k * 64 + (n - 64)];
        g_bt3[n * 64 + k] = __float2half(v);
    } else if (i < 49152) {
        int j = i - 40960, n = j >> 6, k = j & 63;
        float v = (n < 64) ? w4l[k * 64 + n] : w4r[k * 64 + (n - 64)];
        g_bt4[n * 64 + k] = __float2half(v);
    }
}

// ---------------- convert + counts + x->fp16 (fused; N_EDGES == N_NODES*16) --------
__global__ void k_cvt(const void* __restrict__ ei, const void* __restrict__ batch,
                      const float* __restrict__ x) {
    int i = blockIdx.x * blockDim.x + threadIdx.x;
    int is64 = g_is64;
    if (i < N_EDGES) {
        int s, d;
        if (is64) {
            s = (int)((const long long*)ei)[i];
            d = (int)((const long long*)ei)[N_EDGES + i];
        } else {
            s = ((const int*)ei)[i];
            d = ((const int*)ei)[N_EDGES + i];
        }
        s = clampN(s, N_NODES);
        d = clampN(d, N_NODES);
        g_src[i] = s;
        g_dst[i] = d;
        atomicAdd(&g_cnt[d], 1);
        float4 v = ((const float4*)x)[i];
        __half2 a = __floats2half2_rn(v.x, v.y);
        __half2 b = __floats2half2_rn(v.z, v.w);
        uint2 u;
        u.x = *(unsigned*)&a;
        u.y = *(unsigned*)&b;
        ((uint2*)g_xh)[i] = u;
    }
    if (i < N_NODES) {
        int b = is64 ? (int)((const long long*)batch)[i] : ((const int*)batch)[i];
        atomicAdd(&g_gcnt[clampN(b, N_GRAPHS)], 1);
    }
}

// ---------------- scan: per-block (A), then fused carry+graph+materialize (BC) -----
__global__ void k_scanA() {
    __shared__ int wsum[32];
    __shared__ int woff[32];
    int tid = threadIdx.x, lane = tid & 31, wid = tid >> 5;
    int i = blockIdx.x * 1024 + tid;
    int c = (i < N_NODES) ? g_cnt[i] : 0;
    int incl = c;
    #pragma unroll
    for (int o = 1; o < 32; o <<= 1) {
        int v = __shfl_up_sync(0xffffffffu, incl, o);
        if (lane >= o) incl += v;
    }
    if (lane == 31) wsum[wid] = incl;
    __syncthreads();
    if (wid == 0) {
        int v = wsum[lane];
        int s = v;
        #pragma unroll
        for (int o = 1; o < 32; o <<= 1) {
            int t = __shfl_up_sync(0xffffffffu, s, o);
            if (lane >= o) s += t;
        }
        woff[lane] = s - v;
        if (lane == 31) wsum[0] = s;
    }
    __syncthreads();
    int excl = woff[wid] + (incl - c);
    if (i < N_NODES) g_ptr[i] = excl;
    if (tid == 0) g_bsum[blockIdx.x] = wsum[0];
}

__global__ void k_scanBC() {
    __shared__ int wsum[32];
    int tid = threadIdx.x, lane = tid & 31, wid = tid >> 5;
    if (wid == 0) {
        int carry = 0;
        for (int base = 0; base < SCAN_BLOCKS; base += 32) {
            int idx = base + lane;
            int v = (idx < SCAN_BLOCKS) ? g_bsum[idx] : 0;
            int s = v;
            #pragma unroll
            for (int o = 1; o < 32; o <<= 1) {
                int t = __shfl_up_sync(0xffffffffu, s, o);
                if (lane >= o) s += t;
            }
            if (idx < SCAN_BLOCKS) g_boff[idx] = carry + s - v;
            carry += __shfl_sync(0xffffffffu, s, 31);
        }
        if (lane == 0) g_ptr[N_NODES] = carry;
    }
    __syncthreads();
    {
        int c = g_gcnt[tid];
        int incl = c;
        #pragma unroll
        for (int o = 1; o < 32; o <<= 1) {
            int v = __shfl_up_sync(0xffffffffu, incl, o);
            if (lane >= o) incl += v;
        }
        if (lane == 31) wsum[wid] = incl;
        __syncthreads();
        if (wid == 0) {
            int v = wsum[lane];
            int s = v;
            #pragma unroll
            for (int o = 1; o < 32; o <<= 1) {
                int t = __shfl_up_sync(0xffffffffu, s, o);
                if (lane >= o) s += t;
            }
            wsum[lane] = s - v;
        }
        __syncthreads();
        int excl = wsum[wid] + (incl - c);
        g_gptr[tid] = excl;
        if (tid == 1023) g_gptr[N_GRAPHS] = excl + c;
    }
    __syncthreads();
    for (int base = 0; base < N_NODES; base += 1024) {
        int i = base + tid;
        if (i < N_NODES) {
            int p = g_ptr[i] + g_boff[i >> 10];
            g_ptr[i] = p;
            g_fill[i] = p;
            int c = g_cnt[i];
            g_deginv[i] = 1.0f / (float)(c > 0 ? c : 1);
        }
    }
}

__global__ void k_fill() {
    int e = blockIdx.x * blockDim.x + threadIdx.x;
    if (e < N_EDGES) {
        int p = atomicAdd(&g_fill[g_dst[e]], 1);
        g_srcbuf[clampN(p, N_EDGES)] = g_src[e];
    }
}

// ---------------- aggregation (fp16 gather): warp/node, half-warp/edge ----------------
// COMBINE=false: g_aggx[n] = mean_{src} g_xh[src]                      (fp32 out)
// COMBINE=true : g_hh[n,0:64] = fp16(relu(mean g_yh[src] + bias + g_ys[n]))
template <bool COMBINE>
__global__ void k_aggh(const float* __restrict__ bias) {
    const __half* Yh = COMBINE ? g_yh : g_xh;
    int node = (blockIdx.x * blockDim.x + threadIdx.x) >> 5;
    if (node >= N_NODES) return;
    int lane = threadIdx.x & 31;
    int hw = lane >> 4, l16 = lane & 15;
    int p0 = g_ptr[node], p1 = g_ptr[node + 1];
    if (p1 > N_EDGES) p1 = N_EDGES;
    if (p0 < 0) p0 = 0;
    float ax = 0.f, ay = 0.f, az = 0.f, aw = 0.f;
    for (int base = p0; base < p1; base += 32) {
        int idx = base + lane;
        int s = (idx < p1) ? g_srcbuf[idx] : 0;
        int m = p1 - base;
        if (m > 32) m = 32;
        for (int j = 0; j < m; j += 2) {
            int ss = __shfl_sync(0xffffffffu, s, j + hw);
            if (j + hw < m) {
                uint2 u = *(const uint2*)(Yh + (size_t)ss * 64 + l16 * 4);
                float2 f0 = __half22float2(*(const __half2*)&u.x);
                float2 f1 = __half22float2(*(const __half2*)&u.y);
                ax += f0.x; ay += f0.y; az += f1.x; aw += f1.y;
            }
        }
    }
    ax += __shfl_xor_sync(0xffffffffu, ax, 16);
    ay += __shfl_xor_sync(0xffffffffu, ay, 16);
    az += __shfl_xor_sync(0xffffffffu, az, 16);
    aw += __shfl_xor_sync(0xffffffffu, aw, 16);
    float inv = g_deginv[node];
    ax *= inv; ay *= inv; az *= inv; aw *= inv;
    if (COMBINE) {
        float4 sv = ((const float4*)(g_ys + (size_t)node * 64))[l16];
        float4 bv = ((const float4*)bias)[l16];
        ax = fmaxf(ax + bv.x + sv.x, 0.f);
        ay = fmaxf(ay + bv.y + sv.y, 0.f);
        az = fmaxf(az + bv.z + sv.z, 0.f);
        aw = fmaxf(aw + bv.w + sv.w, 0.f);
        if (hw == 0) {
            __half2 h0 = __floats2half2_rn(ax, ay);
            __half2 h1 = __floats2half2_rn(az, aw);
            uint2 u;
            u.x = *(unsigned*)&h0;
            u.y = *(unsigned*)&h1;
            *(uint2*)(g_hh + (size_t)node * 64 + l16 * 4) = u;
        }
    } else if (hw == 0) {
        float4 o; o.x = ax; o.y = ay; o.z = az; o.w = aw;
        ((float4*)(g_aggx + (size_t)node * 64))[l16] = o;
    }
}

// ---------------- HMMA GEMM: C[128-tile, 128] = A @ Bt^T (mma.sync m16n8k16) --------
// fp16 A/B, fp32 accumulate. KT = 64 or 128 (64-K slabs in shared).
// ROWCAT: A = [g_aggx | x] fp32->fp16 on stage.  L1OUT: relu(+bias) -> g_hh[,128] fp16.
// else split: cols 0:64 (warpCol 0) -> g_yh fp16, cols 64:128 (warpCol 1) -> g_ys fp32.
#define SKH 72  // padded shared K-stride in halves (144 B rows: 16B-aligned, ldsm clean)
template <int KT, bool ROWCAT, bool L1OUT, int BTSEL>
__global__ void k_mma(const float* __restrict__ xExt, const float* __restrict__ bias) {
    __shared__ __half sA[128 * SKH];  // 18 KB
    __shared__ __half sB[128 * SKH];  // 18 KB
    __shared__ float sBias[128];
    int tid = threadIdx.x, wid = tid >> 5, lane = tid & 31;
    int warpRow = wid & 3, warpCol = wid >> 2;
    int row0 = blockIdx.x * 128;
    if (L1OUT && tid < 128) sBias[tid] = bias[tid];

    float acc[2][8][4];
    #pragma unroll
    for (int mt = 0; mt < 2; mt++)
        #pragma unroll
        for (int nt = 0; nt < 8; nt++)
            #pragma unroll
            for (int q = 0; q < 4; q++) acc[mt][nt][q] = 0.f;

    uint32_t aBase = s2u(sA), bBase = s2u(sB);
    int mi = lane >> 3, lr = lane & 7;
    // A frag addrs: m0 rows+0 k0 | m1 rows+8 k0 | m2 rows+0 k8 | m3 rows+8 k8
    uint32_t aAddr0 = aBase +
        (uint32_t)(((warpRow * 32 + (mi & 1) * 8 + lr) * SKH + (mi >> 1) * 8) * 2);
    // B frag addrs (Bt n-major): m0 n+0 k0 | m1 n+0 k8 | m2 n+8 k0 | m3 n+8 k8
    uint32_t bAddr0 = bBase +
        (uint32_t)(((warpCol * 64 + (mi >> 1) * 8 + lr) * SKH + (mi & 1) * 8) * 2);
    const __half* Bt = btp<BTSEL>();

    for (int p = 0; p < KT / 64; p++) {
        int kc = p * 64;
        // stage A: 128 rows x 64 K fp16
        for (int t = tid; t < 1024; t += 256) {
            int r = t >> 3, q = (t & 7) * 8;
            int row = row0 + r;
            uint4 u = make_uint4(0, 0, 0, 0);
            if (row < N_NODES) {
                if (ROWCAT) {
                    const float* src = (p == 0) ? (g_aggx + (size_t)row * 64 + q)
                                                : (xExt + (size_t)row * 64 + q);
                    float4 f0 = *(const float4*)src;
                    float4 f1 = *(const float4*)(src + 4);
                    __half2 h0 = __floats2half2_rn(f0.x, f0.y);
                    __half2 h1 = __floats2half2_rn(f0.z, f0.w);
                    __half2 h2 = __floats2half2_rn(f1.x, f1.y);
                    __half2 h3 = __floats2half2_rn(f1.z, f1.w);
                    u.x = *(unsigned*)&h0; u.y = *(unsigned*)&h1;
                    u.z = *(unsigned*)&h2; u.w = *(unsigned*)&h3;
                } else {
                    u = *(const uint4*)(g_hh + (size_t)row * KT + kc + q);
                }
            }
            *(uint4*)(sA + r * SKH + q) = u;
        }
        // stage B: 128 n-rows x 64 K fp16 from Bt
        for (int t = tid; t < 1024; t += 256) {
            int n = t >> 3, q = (t & 7) * 8;
            uint4 u = *(const uint4*)(Bt + n * KT + kc + q);
            *(uint4*)(sB + n * SKH + q) = u;
        }
        __syncthreads();

        #pragma unroll
        for (int ks = 0; ks < 4; ks++) {
            uint32_t koff = (uint32_t)(ks * 32);  // 16 halves * 2 B
            uint32_t b[4][4];
            #pragma unroll
            for (int nt2 = 0; nt2 < 4; nt2++)
                ldsm_x4(bAddr0 + (uint32_t)(nt2 * 16 * SKH * 2) + koff,
                        b[nt2][0], b[nt2][1], b[nt2][2], b[nt2][3]);
            #pragma unroll
            for (int mt = 0; mt < 2; mt++) {
                uint32_t a[4];
                ldsm_x4(aAddr0 + (uint32_t)(mt * 16 * SKH * 2) + koff,
                        a[0], a[1], a[2], a[3]);
                #pragma unroll
                for (int nt2 = 0; nt2 < 4; nt2++) {
                    mma16816(acc[mt][nt2 * 2 + 0], a, b[nt2][0], b[nt2][1]);
                    mma16816(acc[mt][nt2 * 2 + 1], a, b[nt2][2], b[nt2][3]);
                }
            }
        }
        __syncthreads();
    }

    // epilogue: fragment c layout -> rows gr/gr+8, cols 2*gc,2*gc+1 per n-tile
    int gr = lane >> 2, gc = lane & 3;
    #pragma unroll
    for (int mt = 0; mt < 2; mt++) {
        #pragma unroll
        for (int h = 0; h < 2; h++) {
            int row = row0 + warpRow * 32 + mt * 16 + gr + h * 8;
            if (row < N_NODES) {
                #pragma unroll
                for (int nt = 0; nt < 8; nt++) {
                    int col = warpCol * 64 + nt * 8 + 2 * gc;
                    float v0 = acc[mt][nt][h * 2 + 0];
                    float v1 = acc[mt][nt][h * 2 + 1];
                    if (L1OUT) {
                        v0 = fmaxf(v0 + sBias[col], 0.f);
                        v1 = fmaxf(v1 + sBias[col + 1], 0.f);
                        __half2 hv = __floats2half2_rn(v0, v1);
                        *(unsigned*)(g_hh + (size_t)row * 128 + col) = *(unsigned*)&hv;
                    } else if (warpCol == 0) {
                        __half2 hv = __floats2half2_rn(v0, v1);
                        *(unsigned*)(g_yh + (size_t)row * 64 + col) = *(unsigned*)&hv;
                    } else {
                        float2 fv = make_float2(v0, v1);
                        *(float2*)(g_ys + (size_t)row * 64 + (col - 64)) = fv;
                    }
                }
            }
        }
    }
}

// ---------------- global mean pool (batch sorted -> contiguous segments) ----------------
__global__ void k_pool() {
    int g = blockIdx.x;
    int c = threadIdx.x;
    int r0 = g_gptr[g], r1 = g_gptr[g + 1];
    if (r1 > N_NODES) r1 = N_NODES;
    if (r0 < 0) r0 = 0;
    float acc = 0.f;
    for (int r = r0; r < r1; r++) acc += __half2float(g_hh[(size_t)r * 64 + c]);
    int cnt = r1 - r0;
    g_pool[g * 64 + c] = acc / (float)(cnt > 0 ? cnt : 1);
}

// ---------------- MLP head: 1024 rows, one thread per row ----------------
__global__ void k_mlp(const float* __restrict__ w1, const float* __restrict__ b1,
                      const float* __restrict__ w2, const float* __restrict__ b2,
                      const float* __restrict__ w3, const float* __restrict__ b3,
                      const float* __restrict__ w4, const float* __restrict__ b4,
                      float* __restrict__ out) {
    __shared__ float s1[64 * 64], sb1[64], s2[64 * 32], sb2[32], s3[32 * 32], sb3[32], s4[32];
    __shared__ float sb4;
    int tid = threadIdx.x;
    for (int i = tid; i < 4096; i += 256) s1[i] = w1[i];
    for (int i = tid; i < 2048; i += 256) s2[i] = w2[i];
    for (int i = tid; i < 1024; i += 256) s3[i] = w3[i];
    if (tid < 64) sb1[tid] = b1[tid];
    if (tid < 32) { sb2[tid] = b2[tid]; sb3[tid] = b3[tid]; s4[tid] = w4[tid]; }
    if (tid == 0) sb4 = b4[0];
    __syncthreads();
    int row = blockIdx.x * 256 + tid;
    if (row >= N_GRAPHS) return;
    float gin[64];
    #pragma unroll
    for (int k = 0; k < 64; k++) gin[k] = g_pool[row * 64 + k];
    float h1[64];
    for (int j = 0; j < 64; j++) {
        float a = sb1[j];
        #pragma unroll
        for (int k = 0; k < 64; k++) a += gin[k] * s1[k * 64 + j];
        h1[j] = fmaxf(a, 0.f);
    }
    float h2[32];
    for (int j = 0; j < 32; j++) {
        float a = sb2[j];
        #pragma unroll
        for (int k = 0; k < 64; k++) a += h1[k] * s2[k * 32 + j];
        h2[j] = fmaxf(a, 0.f);
    }
    float h3[32];
    for (int j = 0; j < 32; j++) {
        float a = sb3[j];
        #pragma unroll
        for (int k = 0; k < 32; k++) a += h2[k] * s3[k * 32 + j];
        h3[j] = fmaxf(a, 0.f);
    }
    float o = sb4;
    #pragma unroll
    for (int k = 0; k < 32; k++) o += h3[k] * s4[k];
    out[row] = o;
}

// ---------------- host launch: KERNEL LAUNCHES ONLY ----------------
extern "C" void kernel_launch(void* const* d_in, const int* in_sizes, int n_in,
                              void* d_out, int out_size) {
    const float* x = (const float*)d_in[0];
    const void* ei = d_in[1];
    const void* batch = d_in[2];
    const float* c1wl = (const float*)d_in[3];
    const float* c1bl = (const float*)d_in[4];
    const float* c1wr = (const float*)d_in[5];
    const float* c2wl = (const float*)d_in[6];
    const float* c2bl = (const float*)d_in[7];
    const float* c2wr = (const float*)d_in[8];
    const float* c3wl = (const float*)d_in[9];
    const float* c3bl = (const float*)d_in[10];
    const float* c3wr = (const float*)d_in[11];
    const float* c4wl = (const float*)d_in[12];
    const float* c4bl = (const float*)d_in[13];
    const float* c4wr = (const float*)d_in[14];
    const float* l1w = (const float*)d_in[15];
    const float* l1b = (const float*)d_in[16];
    const float* l2w = (const float*)d_in[17];
    const float* l2b = (const float*)d_in[18];
    const float* l3w = (const float*)d_in[19];
    const float* l3b = (const float*)d_in[20];
    const float* l4w = (const float*)d_in[21];
    const float* l4b = (const float*)d_in[22];
    float* out = (float*)d_out;

    int aggBlocks = (N_NODES * 32 + 255) / 256;
    int mmaBlocks = (N_NODES + 127) / 128;

    // launches 0-4: setup + CSR; launch 5 (ncu -s 5) = k_aggh (measurement target)
    k_zero<<<(N_NODES + 255) / 256, 256>>>((const unsigned int*)ei,
        c1wl, c1wr, c2wl, c2wr, c3wl, c3wr, c4wl, c4wr);
    k_cvt<<<(N_EDGES + 255) / 256, 256>>>(ei, batch, x);
    k_scanA<<<SCAN_BLOCKS, 1024>>>();
    k_scanBC<<<1, 1024>>>();
    k_fill<<<(N_EDGES + 255) / 256, 256>>>();

    // layer 1: aggx = mean(xh[src]); h1 = relu([aggx|x] @ [wl;wr] + b1) -> g_hh[,128] fp16
    k_aggh<false><<<aggBlocks, 256>>>(nullptr);
    k_mma<128, true, true, 1><<<mmaBlocks, 256>>>(x, c1bl);

    // layer 2: y = h1 @ [wl|wr] split; h2 = relu(mean(yh[src]) + b2 + ys) -> g_hh[,64] fp16
    k_mma<128, false, false, 2><<<mmaBlocks, 256>>>(nullptr, nullptr);
    k_aggh<true><<<aggBlocks, 256>>>(c2bl);

    // layer 3
    k_mma<64, false, false, 3><<<mmaBlocks, 256>>>(nullptr, nullptr);
    k_aggh<true><<<aggBlocks, 256>>>(c3bl);

    // layer 4
    k_mma<64, false, false, 4><<<mmaBlocks, 256>>>(nullptr, nullptr);
    k_aggh<true><<<aggBlocks, 256>>>(c4bl);

    // pool + MLP head
    k_pool<<<N_GRAPHS, 64>>>();
    k_mlp<<<(N_GRAPHS + 255) / 256, 256>>>(l1w, l1b, l2w, l2b, l3w, l3b, l4w, l4b, out);
}

// round 13
// speedup vs baseline: 1.5810x; 1.5810x over previous
#include <cuda_runtime.h>
#include <cuda_fp16.h>
#include <cstdint>

#define N_NODES 100000
#define N_EDGES 1600000
#define N_GRAPHS 1024
#define SCAN_BLOCKS ((N_NODES + 1023) / 1024)  // 98

// ---------------- scratch (static __device__; no allocation) ----------------
__device__ int    g_is64;
__device__ int    g_src[N_EDGES];
__device__ int    g_dst[N_EDGES];
__device__ int    g_cnt[N_NODES];
__device__ int    g_ptr[N_NODES + 1];
__device__ int    g_fill[N_NODES];
__device__ int    g_srcbuf[N_EDGES];
__device__ float  g_deginv[N_NODES];
__device__ int    g_gcnt[N_GRAPHS];
__device__ int    g_gptr[N_GRAPHS + 1];
__device__ int    g_bsum[SCAN_BLOCKS];
__device__ int    g_boff[SCAN_BLOCKS];
__device__ float  g_aggx[N_NODES * 64];                 // layer-1 aggregated x (fp32)
__device__ __half g_xh[(size_t)N_NODES * 64];           // fp16 x (layer-1 gather)
__device__ __half g_hh[(size_t)N_NODES * 128];          // fp16 activations (GEMM A source)
__device__ __half g_yh[(size_t)N_NODES * 64];           // fp16 gather half of y
__device__ float  g_ys[(size_t)N_NODES * 64];           // fp32 self half of y
__device__ float  g_pool[N_GRAPHS * 64];
__device__ __half g_bt1[128 * 128];                     // W^T fp16 per layer (Bt[n][k])
__device__ __half g_bt2[128 * 128];
__device__ __half g_bt3[128 * 64];
__device__ __half g_bt4[128 * 64];

__device__ __forceinline__ int clampN(int v, int n) {
    return ((unsigned)v < (unsigned)n) ? v : 0;
}

template <int B>
__device__ __forceinline__ const __half* btp() {
    if (B == 1) return g_bt1;
    if (B == 2) return g_bt2;
    if (B == 3) return g_bt3;
    return g_bt4;
}

__device__ __forceinline__ uint32_t s2u(const void* p) {
    uint32_t a;
    asm("{ .reg .u64 t; cvta.to.shared.u64 t, %1; cvt.u32.u64 %0, t; }" : "=r"(a) : "l"(p));
    return a;
}

__device__ __forceinline__ void ldsm_x4(uint32_t addr, uint32_t& r0, uint32_t& r1,
                                        uint32_t& r2, uint32_t& r3) {
    asm volatile("ldmatrix.sync.aligned.m8n8.x4.shared.b16 {%0,%1,%2,%3}, [%4];"
                 : "=r"(r0), "=r"(r1), "=r"(r2), "=r"(r3) : "r"(addr));
}

__device__ __forceinline__ void mma16816(float* d, const uint32_t* a,
                                         uint32_t b0, uint32_t b1) {
    asm volatile(
        "mma.sync.aligned.m16n8k16.row.col.f32.f16.f16.f32 "
        "{%0,%1,%2,%3}, {%4,%5,%6,%7}, {%8,%9}, {%0,%1,%2,%3};"
        : "+f"(d[0]), "+f"(d[1]), "+f"(d[2]), "+f"(d[3])
        : "r"(a[0]), "r"(a[1]), "r"(a[2]), "r"(a[3]), "r"(b0), "r"(b1));
}

// ---------------- zero + detect + weight-transpose prep (fused) ----------------
__global__ void k_zero(const unsigned int* __restrict__ ei_raw,
                       const float* __restrict__ w1l, const float* __restrict__ w1r,
                       const float* __restrict__ w2l, const float* __restrict__ w2r,
                       const float* __restrict__ w3l, const float* __restrict__ w3r,
                       const float* __restrict__ w4l, const float* __restrict__ w4r) {
    int i = blockIdx.x * blockDim.x + threadIdx.x;
    if (i < N_NODES) g_cnt[i] = 0;
    if (i < N_GRAPHS) g_gcnt[i] = 0;
    if (i == 0) {
        int is64 = 1;
        for (int t = 0; t < 128; t++) {
            if (ei_raw[2 * t + 1] != 0u) { is64 = 0; break; }
        }
        g_is64 = is64;
    }
    // Bt[n][k] = W[k][n] in fp16
    if (i < 16384) {
        int n = i >> 7, k = i & 127;
        float v = (k < 64) ? w1l[k * 128 + n] : w1r[(k - 64) * 128 + n];
        g_bt1[n * 128 + k] = __float2half(v);
    } else if (i < 32768) {
        int j = i - 16384, n = j >> 7, k = j & 127;
        float v = (n < 64) ? w2l[k * 64 + n] : w2r[k * 64 + (n - 64)];
        g_bt2[n * 128 + k] = __float2half(v);
    } else if (i < 40960) {
        int j = i - 32768, n = j >> 6, k = j & 63;
        float v = (n < 64) ? w3l[k * 64 + n] : w3r[k * 64 + (n - 64)];
        g_bt3[n * 64 + k] = __float2half(v);
    } else if (i < 49152) {
        int j = i - 40960, n = j >> 6, k = j & 63;
        float v = (n < 64) ? w4l[k * 64 + n] : w4r[k * 64 + (n - 64)];
        g_bt4[n * 64 + k] = __float2half(v);
    }
}

// ---------------- convert + counts + x->fp16 (fused; N_EDGES == N_NODES*16) --------
__global__ void k_cvt(const void* __restrict__ ei, const void* __restrict__ batch,
                      const float* __restrict__ x) {
    int i = blockIdx.x * blockDim.x + threadIdx.x;
    int is64 = g_is64;
    if (i < N_EDGES) {
        int s, d;
        if (is64) {
            s = (int)((const long long*)ei)[i];
            d = (int)((const long long*)ei)[N_EDGES + i];
        } else {
            s = ((const int*)ei)[i];
            d = ((const int*)ei)[N_EDGES + i];
        }
        s = clampN(s, N_NODES);
        d = clampN(d, N_NODES);
        g_src[i] = s;
        g_dst[i] = d;
        atomicAdd(&g_cnt[d], 1);
        float4 v = ((const float4*)x)[i];
        __half2 a = __floats2half2_rn(v.x, v.y);
        __half2 b = __floats2half2_rn(v.z, v.w);
        uint2 u;
        u.x = *(unsigned*)&a;
        u.y = *(unsigned*)&b;
        ((uint2*)g_xh)[i] = u;
    }
    if (i < N_NODES) {
        int b = is64 ? (int)((const long long*)batch)[i] : ((const int*)batch)[i];
        atomicAdd(&g_gcnt[clampN(b, N_GRAPHS)], 1);
    }
}

// ---------------- parallel 3-pass scan ----------------
__global__ void k_scanA() {
    __shared__ int wsum[32];
    __shared__ int woff[32];
    int tid = threadIdx.x, lane = tid & 31, wid = tid >> 5;
    int i = blockIdx.x * 1024 + tid;
    int c = (i < N_NODES) ? g_cnt[i] : 0;
    int incl = c;
    #pragma unroll
    for (int o = 1; o < 32; o <<= 1) {
        int v = __shfl_up_sync(0xffffffffu, incl, o);
        if (lane >= o) incl += v;
    }
    if (lane == 31) wsum[wid] = incl;
    __syncthreads();
    if (wid == 0) {
        int v = wsum[lane];
        int s = v;
        #pragma unroll
        for (int o = 1; o < 32; o <<= 1) {
            int t = __shfl_up_sync(0xffffffffu, s, o);
            if (lane >= o) s += t;
        }
        woff[lane] = s - v;
        if (lane == 31) wsum[0] = s;
    }
    __syncthreads();
    int excl = woff[wid] + (incl - c);
    if (i < N_NODES) g_ptr[i] = excl;
    if (tid == 0) g_bsum[blockIdx.x] = wsum[0];
}

__global__ void k_scanB() {
    __shared__ int wsum[32];
    int tid = threadIdx.x, lane = tid & 31, wid = tid >> 5;
    if (wid == 0) {
        int carry = 0;
        for (int base = 0; base < SCAN_BLOCKS; base += 32) {
            int idx = base + lane;
            int v = (idx < SCAN_BLOCKS) ? g_bsum[idx] : 0;
            int s = v;
            #pragma unroll
            for (int o = 1; o < 32; o <<= 1) {
                int t = __shfl_up_sync(0xffffffffu, s, o);
                if (lane >= o) s += t;
            }
            if (idx < SCAN_BLOCKS) g_boff[idx] = carry + s - v;
            carry += __shfl_sync(0xffffffffu, s, 31);
        }
        if (lane == 0) g_ptr[N_NODES] = carry;
    }
    __syncthreads();
    {
        int c = g_gcnt[tid];
        int incl = c;
        #pragma unroll
        for (int o = 1; o < 32; o <<= 1) {
            int v = __shfl_up_sync(0xffffffffu, incl, o);
            if (lane >= o) incl += v;
        }
        if (lane == 31) wsum[wid] = incl;
        __syncthreads();
        if (wid == 0) {
            int v = wsum[lane];
            int s = v;
            #pragma unroll
            for (int o = 1; o < 32; o <<= 1) {
                int t = __shfl_up_sync(0xffffffffu, s, o);
                if (lane >= o) s += t;
            }
            wsum[lane] = s - v;
        }
        __syncthreads();
        int excl = wsum[wid] + (incl - c);
        g_gptr[tid] = excl;
        if (tid == 1023) g_gptr[N_GRAPHS] = excl + c;
    }
}

// parallel materialize: offset add + fill/deginv
__global__ void k_scanC() {
    int i = blockIdx.x * blockDim.x + threadIdx.x;
    if (i < N_NODES) {
        int p = g_ptr[i] + g_boff[i >> 10];
        g_ptr[i] = p;
        g_fill[i] = p;
        int c = g_cnt[i];
        g_deginv[i] = 1.0f / (float)(c > 0 ? c : 1);
    }
}

__global__ void k_fill() {
    int e = blockIdx.x * blockDim.x + threadIdx.x;
    if (e < N_EDGES) {
        int p = atomicAdd(&g_fill[g_dst[e]], 1);
        g_srcbuf[clampN(p, N_EDGES)] = g_src[e];
    }
}

// ---------------- aggregation (fp16 gather): warp/node, half-warp/edge ----------------
// COMBINE=false: g_aggx[n] = mean_{src} g_xh[src]                      (fp32 out)
// COMBINE=true : g_hh[n,0:64] = fp16(relu(mean g_yh[src] + bias + g_ys[n]))
template <bool COMBINE>
__global__ void k_aggh(const float* __restrict__ bias) {
    const __half* Yh = COMBINE ? g_yh : g_xh;
    int node = (blockIdx.x * blockDim.x + threadIdx.x) >> 5;
    if (node >= N_NODES) return;
    int lane = threadIdx.x & 31;
    int hw = lane >> 4, l16 = lane & 15;
    int p0 = g_ptr[node], p1 = g_ptr[node + 1];
    if (p1 > N_EDGES) p1 = N_EDGES;
    if (p0 < 0) p0 = 0;
    float ax = 0.f, ay = 0.f, az = 0.f, aw = 0.f;
    for (int base = p0; base < p1; base += 32) {
        int idx = base + lane;
        int s = (idx < p1) ? g_srcbuf[idx] : 0;
        int m = p1 - base;
        if (m > 32) m = 32;
        for (int j = 0; j < m; j += 2) {
            int ss = __shfl_sync(0xffffffffu, s, j + hw);
            if (j + hw < m) {
                uint2 u = *(const uint2*)(Yh + (size_t)ss * 64 + l16 * 4);
                float2 f0 = __half22float2(*(const __half2*)&u.x);
                float2 f1 = __half22float2(*(const __half2*)&u.y);
                ax += f0.x; ay += f0.y; az += f1.x; aw += f1.y;
            }
        }
    }
    ax += __shfl_xor_sync(0xffffffffu, ax, 16);
    ay += __shfl_xor_sync(0xffffffffu, ay, 16);
    az += __shfl_xor_sync(0xffffffffu, az, 16);
    aw += __shfl_xor_sync(0xffffffffu, aw, 16);
    float inv = g_deginv[node];
    ax *= inv; ay *= inv; az *= inv; aw *= inv;
    if (COMBINE) {
        float4 sv = ((const float4*)(g_ys + (size_t)node * 64))[l16];
        float4 bv = ((const float4*)bias)[l16];
        ax = fmaxf(ax + bv.x + sv.x, 0.f);
        ay = fmaxf(ay + bv.y + sv.y, 0.f);
        az = fmaxf(az + bv.z + sv.z, 0.f);
        aw = fmaxf(aw + bv.w + sv.w, 0.f);
        if (hw == 0) {
            __half2 h0 = __floats2half2_rn(ax, ay);
            __half2 h1 = __floats2half2_rn(az, aw);
            uint2 u;
            u.x = *(unsigned*)&h0;
            u.y = *(unsigned*)&h1;
            *(uint2*)(g_hh + (size_t)node * 64 + l16 * 4) = u;
        }
    } else if (hw == 0) {
        float4 o; o.x = ax; o.y = ay; o.z = az; o.w = aw;
        ((float4*)(g_aggx + (size_t)node * 64))[l16] = o;
    }
}

// ---------------- HMMA GEMM: C[128-tile, 128] = A @ Bt^T (mma.sync m16n8k16) --------
// fp16 A/B, fp32 accumulate. KT = 64 or 128 (64-K slabs in shared).
// ROWCAT: A = [g_aggx | x] fp32->fp16 on stage.  L1OUT: relu(+bias) -> g_hh[,128] fp16.
// else split: cols 0:64 (warpCol 0) -> g_yh fp16, cols 64:128 (warpCol 1) -> g_ys fp32.
#define SKH 72  // padded shared K-stride in halves (144 B rows: 16B-aligned, ldsm clean)
template <int KT, bool ROWCAT, bool L1OUT, int BTSEL>
__global__ void k_mma(const float* __restrict__ xExt, const float* __restrict__ bias) {
    __shared__ __half sA[128 * SKH];  // 18 KB
    __shared__ __half sB[128 * SKH];  // 18 KB
    __shared__ float sBias[128];
    int tid = threadIdx.x, wid = tid >> 5, lane = tid & 31;
    int warpRow = wid & 3, warpCol = wid >> 2;
    int row0 = blockIdx.x * 128;
    if (L1OUT && tid < 128) sBias[tid] = bias[tid];

    float acc[2][8][4];
    #pragma unroll
    for (int mt = 0; mt < 2; mt++)
        #pragma unroll
        for (int nt = 0; nt < 8; nt++)
            #pragma unroll
            for (int q = 0; q < 4; q++) acc[mt][nt][q] = 0.f;

    uint32_t aBase = s2u(sA), bBase = s2u(sB);
    int mi = lane >> 3, lr = lane & 7;
    uint32_t aAddr0 = aBase +
        (uint32_t)(((warpRow * 32 + (mi & 1) * 8 + lr) * SKH + (mi >> 1) * 8) * 2);
    uint32_t bAddr0 = bBase +
        (uint32_t)(((warpCol * 64 + (mi >> 1) * 8 + lr) * SKH + (mi & 1) * 8) * 2);
    const __half* Bt = btp<BTSEL>();

    for (int p = 0; p < KT / 64; p++) {
        int kc = p * 64;
        for (int t = tid; t < 1024; t += 256) {
            int r = t >> 3, q = (t & 7) * 8;
            int row = row0 + r;
            uint4 u = make_uint4(0, 0, 0, 0);
            if (row < N_NODES) {
                if (ROWCAT) {
                    const float* src = (p == 0) ? (g_aggx + (size_t)row * 64 + q)
                                                : (xExt + (size_t)row * 64 + q);
                    float4 f0 = *(const float4*)src;
                    float4 f1 = *(const float4*)(src + 4);
                    __half2 h0 = __floats2half2_rn(f0.x, f0.y);
                    __half2 h1 = __floats2half2_rn(f0.z, f0.w);
                    __half2 h2 = __floats2half2_rn(f1.x, f1.y);
                    __half2 h3 = __floats2half2_rn(f1.z, f1.w);
                    u.x = *(unsigned*)&h0; u.y = *(unsigned*)&h1;
                    u.z = *(unsigned*)&h2; u.w = *(unsigned*)&h3;
                } else {
                    u = *(const uint4*)(g_hh + (size_t)row * KT + kc + q);
                }
            }
            *(uint4*)(sA + r * SKH + q) = u;
        }
        for (int t = tid; t < 1024; t += 256) {
            int n = t >> 3, q = (t & 7) * 8;
            uint4 u = *(const uint4*)(Bt + n * KT + kc + q);
            *(uint4*)(sB + n * SKH + q) = u;
        }
        __syncthreads();

        #pragma unroll
        for (int ks = 0; ks < 4; ks++) {
            uint32_t koff = (uint32_t)(ks * 32);
            uint32_t b[4][4];
            #pragma unroll
            for (int nt2 = 0; nt2 < 4; nt2++)
                ldsm_x4(bAddr0 + (uint32_t)(nt2 * 16 * SKH * 2) + koff,
                        b[nt2][0], b[nt2][1], b[nt2][2], b[nt2][3]);
            #pragma unroll
            for (int mt = 0; mt < 2; mt++) {
                uint32_t a[4];
                ldsm_x4(aAddr0 + (uint32_t)(mt * 16 * SKH * 2) + koff,
                        a[0], a[1], a[2], a[3]);
                #pragma unroll
                for (int nt2 = 0; nt2 < 4; nt2++) {
                    mma16816(acc[mt][nt2 * 2 + 0], a, b[nt2][0], b[nt2][1]);
                    mma16816(acc[mt][nt2 * 2 + 1], a, b[nt2][2], b[nt2][3]);
                }
            }
        }
        __syncthreads();
    }

    int gr = lane >> 2, gc = lane & 3;
    #pragma unroll
    for (int mt = 0; mt < 2; mt++) {
        #pragma unroll
        for (int h = 0; h < 2; h++) {
            int row = row0 + warpRow * 32 + mt * 16 + gr + h * 8;
            if (row < N_NODES) {
                #pragma unroll
                for (int nt = 0; nt < 8; nt++) {
                    int col = warpCol * 64 + nt * 8 + 2 * gc;
                    float v0 = acc[mt][nt][h * 2 + 0];
                    float v1 = acc[mt][nt][h * 2 + 1];
                    if (L1OUT) {
                        v0 = fmaxf(v0 + sBias[col], 0.f);
                        v1 = fmaxf(v1 + sBias[col + 1], 0.f);
                        __half2 hv = __floats2half2_rn(v0, v1);
                        *(unsigned*)(g_hh + (size_t)row * 128 + col) = *(unsigned*)&hv;
                    } else if (warpCol == 0) {
                        __half2 hv = __floats2half2_rn(v0, v1);
                        *(unsigned*)(g_yh + (size_t)row * 64 + col) = *(unsigned*)&hv;
                    } else {
                        float2 fv = make_float2(v0, v1);
                        *(float2*)(g_ys + (size_t)row * 64 + (col - 64)) = fv;
                    }
                }
            }
        }
    }
}

// ---------------- global mean pool (batch sorted -> contiguous segments) ----------------
__global__ void k_pool() {
    int g = blockIdx.x;
    int c = threadIdx.x;
    int r0 = g_gptr[g], r1 = g_gptr[g + 1];
    if (r1 > N_NODES) r1 = N_NODES;
    if (r0 < 0) r0 = 0;
    float acc = 0.f;
    for (int r = r0; r < r1; r++) acc += __half2float(g_hh[(size_t)r * 64 + c]);
    int cnt = r1 - r0;
    g_pool[g * 64 + c] = acc / (float)(cnt > 0 ? cnt : 1);
}

// ---------------- MLP head: 1024 rows, one thread per row ----------------
__global__ void k_mlp(const float* __restrict__ w1, const float* __restrict__ b1,
                      const float* __restrict__ w2, const float* __restrict__ b2,
                      const float* __restrict__ w3, const float* __restrict__ b3,
                      const float* __restrict__ w4, const float* __restrict__ b4,
                      float* __restrict__ out) {
    __shared__ float s1[64 * 64], sb1[64], s2[64 * 32], sb2[32], s3[32 * 32], sb3[32], s4[32];
    __shared__ float sb4;
    int tid = threadIdx.x;
    for (int i = tid; i < 4096; i += 256) s1[i] = w1[i];
    for (int i = tid; i < 2048; i += 256) s2[i] = w2[i];
    for (int i = tid; i < 1024; i += 256) s3[i] = w3[i];
    if (tid < 64) sb1[tid] = b1[tid];
    if (tid < 32) { sb2[tid] = b2[tid]; sb3[tid] = b3[tid]; s4[tid] = w4[tid]; }
    if (tid == 0) sb4 = b4[0];
    __syncthreads();
    int row = blockIdx.x * 256 + tid;
    if (row >= N_GRAPHS) return;
    float gin[64];
    #pragma unroll
    for (int k = 0; k < 64; k++) gin[k] = g_pool[row * 64 + k];
    float h1[64];
    for (int j = 0; j < 64; j++) {
        float a = sb1[j];
        #pragma unroll
        for (int k = 0; k < 64; k++) a += gin[k] * s1[k * 64 + j];
        h1[j] = fmaxf(a, 0.f);
    }
    float h2[32];
    for (int j = 0; j < 32; j++) {
        float a = sb2[j];
        #pragma unroll
        for (int k = 0; k < 64; k++) a += h1[k] * s2[k * 32 + j];
        h2[j] = fmaxf(a, 0.f);
    }
    float h3[32];
    for (int j = 0; j < 32; j++) {
        float a = sb3[j];
        #pragma unroll
        for (int k = 0; k < 32; k++) a += h2[k] * s3[k * 32 + j];
        h3[j] = fmaxf(a, 0.f);
    }
    float o = sb4;
    #pragma unroll
    for (int k = 0; k < 32; k++) o += h3[k] * s4[k];
    out[row] = o;
}

// ---------------- host launch: KERNEL LAUNCHES ONLY ----------------
extern "C" void kernel_launch(void* const* d_in, const int* in_sizes, int n_in,
                              void* d_out, int out_size) {
    const float* x = (const float*)d_in[0];
    const void* ei = d_in[1];
    const void* batch = d_in[2];
    const float* c1wl = (const float*)d_in[3];
    const float* c1bl = (const float*)d_in[4];
    const float* c1wr = (const float*)d_in[5];
    const float* c2wl = (const float*)d_in[6];
    const float* c2bl = (const float*)d_in[7];
    const float* c2wr = (const float*)d_in[8];
    const float* c3wl = (const float*)d_in[9];
    const float* c3bl = (const float*)d_in[10];
    const float* c3wr = (const float*)d_in[11];
    const float* c4wl = (const float*)d_in[12];
    const float* c4bl = (const float*)d_in[13];
    const float* c4wr = (const float*)d_in[14];
    const float* l1w = (const float*)d_in[15];
    const float* l1b = (const float*)d_in[16];
    const float* l2w = (const float*)d_in[17];
    const float* l2b = (const float*)d_in[18];
    const float* l3w = (const float*)d_in[19];
    const float* l3b = (const float*)d_in[20];
    const float* l4w = (const float*)d_in[21];
    const float* l4b = (const float*)d_in[22];
    float* out = (float*)d_out;

    int aggBlocks = (N_NODES * 32 + 255) / 256;
    int mmaBlocks = (N_NODES + 127) / 128;

    k_zero<<<(N_NODES + 255) / 256, 256>>>((const unsigned int*)ei,
        c1wl, c1wr, c2wl, c2wr, c3wl, c3wr, c4wl, c4wr);
    k_cvt<<<(N_EDGES + 255) / 256, 256>>>(ei, batch, x);
    k_scanA<<<SCAN_BLOCKS, 1024>>>();
    k_scanB<<<1, 1024>>>();
    k_scanC<<<(N_NODES + 1023) / 1024, 1024>>>();
    k_fill<<<(N_EDGES + 255) / 256, 256>>>();

    // layer 1: aggx = mean(xh[src]); h1 = relu([aggx|x] @ [wl;wr] + b1) -> g_hh[,128] fp16
    k_aggh<false><<<aggBlocks, 256>>>(nullptr);
    k_mma<128, true, true, 1><<<mmaBlocks, 256>>>(x, c1bl);

    // layer 2: y = h1 @ [wl|wr] split; h2 = relu(mean(yh[src]) + b2 + ys) -> g_hh[,64] fp16
    k_mma<128, false, false, 2><<<mmaBlocks, 256>>>(nullptr, nullptr);
    k_aggh<true><<<aggBlocks, 256>>>(c2bl);

    // layer 3
    k_mma<64, false, false, 3><<<mmaBlocks, 256>>>(nullptr, nullptr);
    k_aggh<true><<<aggBlocks, 256>>>(c3bl);

    // layer 4
    k_mma<64, false, false, 4><<<mmaBlocks, 256>>>(nullptr, nullptr);
    k_aggh<true><<<aggBlocks, 256>>>(c4bl);

    // pool + MLP head
    k_pool<<<N_GRAPHS, 64>>>();
    k_mlp<<<(N_GRAPHS + 255) / 256, 256>>>(l1w, l1b, l2w, l2b, l3w, l3b, l4w, l4b, out);
}

// round 14
// speedup vs baseline: 1.7739x; 1.1220x over previous
#include <cuda_runtime.h>
#include <cuda_fp16.h>
#include <cstdint>

#define N_NODES 100000
#define N_EDGES 1600000
#define N_GRAPHS 1024
#define SCAN_BLOCKS ((N_NODES + 1023) / 1024)  // 98

// ---------------- scratch (static __device__; no allocation) ----------------
__device__ int    g_is64;
__device__ int    g_src[N_EDGES];
__device__ int    g_dst[N_EDGES];
__device__ int    g_cnt[N_NODES];
__device__ int    g_ptr[N_NODES + 1];
__device__ int    g_fill[N_NODES];
__device__ int    g_srcbuf[N_EDGES];
__device__ float  g_deginv[N_NODES];
__device__ int    g_gcnt[N_GRAPHS];
__device__ int    g_gptr[N_GRAPHS + 1];
__device__ int    g_bsum[SCAN_BLOCKS];
__device__ int    g_boff[SCAN_BLOCKS];
__device__ float  g_aggx[N_NODES * 64];                 // layer-1 aggregated x (fp32)
__device__ __half g_xh[(size_t)N_NODES * 64];           // fp16 x (layer-1 gather)
__device__ __half g_hh[(size_t)N_NODES * 128];          // fp16 activations (GEMM A source)
__device__ __half g_yh[(size_t)N_NODES * 64];           // fp16 gather half of y
__device__ float  g_ys[(size_t)N_NODES * 64];           // fp32 self half of y
__device__ float  g_pool[N_GRAPHS * 64];
__device__ __half g_bt1[128 * 128];                     // W^T fp16 per layer (Bt[n][k])
__device__ __half g_bt2[128 * 128];
__device__ __half g_bt3[128 * 64];
__device__ __half g_bt4[128 * 64];

__device__ __forceinline__ int clampN(int v, int n) {
    return ((unsigned)v < (unsigned)n) ? v : 0;
}

template <int B>
__device__ __forceinline__ const __half* btp() {
    if (B == 1) return g_bt1;
    if (B == 2) return g_bt2;
    if (B == 3) return g_bt3;
    return g_bt4;
}

__device__ __forceinline__ uint32_t s2u(const void* p) {
    uint32_t a;
    asm("{ .reg .u64 t; cvta.to.shared.u64 t, %1; cvt.u32.u64 %0, t; }" : "=r"(a) : "l"(p));
    return a;
}

__device__ __forceinline__ void ldsm_x4(uint32_t addr, uint32_t& r0, uint32_t& r1,
                                        uint32_t& r2, uint32_t& r3) {
    asm volatile("ldmatrix.sync.aligned.m8n8.x4.shared.b16 {%0,%1,%2,%3}, [%4];"
                 : "=r"(r0), "=r"(r1), "=r"(r2), "=r"(r3) : "r"(addr));
}

__device__ __forceinline__ void mma16816(float* d, const uint32_t* a,
                                         uint32_t b0, uint32_t b1) {
    asm volatile(
        "mma.sync.aligned.m16n8k16.row.col.f32.f16.f16.f32 "
        "{%0,%1,%2,%3}, {%4,%5,%6,%7}, {%8,%9}, {%0,%1,%2,%3};"
        : "+f"(d[0]), "+f"(d[1]), "+f"(d[2]), "+f"(d[3])
        : "r"(a[0]), "r"(a[1]), "r"(a[2]), "r"(a[3]), "r"(b0), "r"(b1));
}

// ---------------- zero + detect + weight-transpose prep (fused) ----------------
__global__ void k_zero(const unsigned int* __restrict__ ei_raw,
                       const float* __restrict__ w1l, const float* __restrict__ w1r,
                       const float* __restrict__ w2l, const float* __restrict__ w2r,
                       const float* __restrict__ w3l, const float* __restrict__ w3r,
                       const float* __restrict__ w4l, const float* __restrict__ w4r) {
    int i = blockIdx.x * blockDim.x + threadIdx.x;
    if (i < N_NODES) g_cnt[i] = 0;
    if (i < N_GRAPHS) g_gcnt[i] = 0;
    if (i == 0) {
        int is64 = 1;
        for (int t = 0; t < 128; t++) {
            if (ei_raw[2 * t + 1] != 0u) { is64 = 0; break; }
        }
        g_is64 = is64;
    }
    // Bt[n][k] = W[k][n] in fp16
    if (i < 16384) {
        int n = i >> 7, k = i & 127;
        float v = (k < 64) ? w1l[k * 128 + n] : w1r[(k - 64) * 128 + n];
        g_bt1[n * 128 + k] = __float2half(v);
    } else if (i < 32768) {
        int j = i - 16384, n = j >> 7, k = j & 127;
        float v = (n < 64) ? w2l[k * 64 + n] : w2r[k * 64 + (n - 64)];
        g_bt2[n * 128 + k] = __float2half(v);
    } else if (i < 40960) {
        int j = i - 32768, n = j >> 6, k = j & 63;
        float v = (n < 64) ? w3l[k * 64 + n] : w3r[k * 64 + (n - 64)];
        g_bt3[n * 64 + k] = __float2half(v);
    } else if (i < 49152) {
        int j = i - 40960, n = j >> 6, k = j & 63;
        float v = (n < 64) ? w4l[k * 64 + n] : w4r[k * 64 + (n - 64)];
        g_bt4[n * 64 + k] = __float2half(v);
    }
}

// ---------------- convert + counts + x->fp16 (fused; N_EDGES == N_NODES*16) --------
__global__ void k_cvt(const void* __restrict__ ei, const void* __restrict__ batch,
                      const float* __restrict__ x) {
    int i = blockIdx.x * blockDim.x + threadIdx.x;
    int is64 = g_is64;
    if (i < N_EDGES) {
        int s, d;
        if (is64) {
            s = (int)((const long long*)ei)[i];
            d = (int)((const long long*)ei)[N_EDGES + i];
        } else {
            s = ((const int*)ei)[i];
            d = ((const int*)ei)[N_EDGES + i];
        }
        s = clampN(s, N_NODES);
        d = clampN(d, N_NODES);
        g_src[i] = s;
        g_dst[i] = d;
        atomicAdd(&g_cnt[d], 1);
        float4 v = ((const float4*)x)[i];
        __half2 a = __floats2half2_rn(v.x, v.y);
        __half2 b = __floats2half2_rn(v.z, v.w);
        uint2 u;
        u.x = *(unsigned*)&a;
        u.y = *(unsigned*)&b;
        ((uint2*)g_xh)[i] = u;
    }
    if (i < N_NODES) {
        int b = is64 ? (int)((const long long*)batch)[i] : ((const int*)batch)[i];
        atomicAdd(&g_gcnt[clampN(b, N_GRAPHS)], 1);
    }
}

// ---------------- parallel 3-pass scan ----------------
__global__ void k_scanA() {
    __shared__ int wsum[32];
    __shared__ int woff[32];
    int tid = threadIdx.x, lane = tid & 31, wid = tid >> 5;
    int i = blockIdx.x * 1024 + tid;
    int c = (i < N_NODES) ? g_cnt[i] : 0;
    int incl = c;
    #pragma unroll
    for (int o = 1; o < 32; o <<= 1) {
        int v = __shfl_up_sync(0xffffffffu, incl, o);
        if (lane >= o) incl += v;
    }
    if (lane == 31) wsum[wid] = incl;
    __syncthreads();
    if (wid == 0) {
        int v = wsum[lane];
        int s = v;
        #pragma unroll
        for (int o = 1; o < 32; o <<= 1) {
            int t = __shfl_up_sync(0xffffffffu, s, o);
            if (lane >= o) s += t;
        }
        woff[lane] = s - v;
        if (lane == 31) wsum[0] = s;
    }
    __syncthreads();
    int excl = woff[wid] + (incl - c);
    if (i < N_NODES) g_ptr[i] = excl;
    if (tid == 0) g_bsum[blockIdx.x] = wsum[0];
}

__global__ void k_scanB() {
    __shared__ int wsum[32];
    int tid = threadIdx.x, lane = tid & 31, wid = tid >> 5;
    if (wid == 0) {
        int carry = 0;
        for (int base = 0; base < SCAN_BLOCKS; base += 32) {
            int idx = base + lane;
            int v = (idx < SCAN_BLOCKS) ? g_bsum[idx] : 0;
            int s = v;
            #pragma unroll
            for (int o = 1; o < 32; o <<= 1) {
                int t = __shfl_up_sync(0xffffffffu, s, o);
                if (lane >= o) s += t;
            }
            if (idx < SCAN_BLOCKS) g_boff[idx] = carry + s - v;
            carry += __shfl_sync(0xffffffffu, s, 31);
        }
        if (lane == 0) g_ptr[N_NODES] = carry;
    }
    __syncthreads();
    {
        int c = g_gcnt[tid];
        int incl = c;
        #pragma unroll
        for (int o = 1; o < 32; o <<= 1) {
            int v = __shfl_up_sync(0xffffffffu, incl, o);
            if (lane >= o) incl += v;
        }
        if (lane == 31) wsum[wid] = incl;
        __syncthreads();
        if (wid == 0) {
            int v = wsum[lane];
            int s = v;
            #pragma unroll
            for (int o = 1; o < 32; o <<= 1) {
                int t = __shfl_up_sync(0xffffffffu, s, o);
                if (lane >= o) s += t;
            }
            wsum[lane] = s - v;
        }
        __syncthreads();
        int excl = wsum[wid] + (incl - c);
        g_gptr[tid] = excl;
        if (tid == 1023) g_gptr[N_GRAPHS] = excl + c;
    }
}

// parallel materialize: offset add + fill/deginv
__global__ void k_scanC() {
    int i = blockIdx.x * blockDim.x + threadIdx.x;
    if (i < N_NODES) {
        int p = g_ptr[i] + g_boff[i >> 10];
        g_ptr[i] = p;
        g_fill[i] = p;
        int c = g_cnt[i];
        g_deginv[i] = 1.0f / (float)(c > 0 ? c : 1);
    }
}

__global__ void k_fill() {
    int e = blockIdx.x * blockDim.x + threadIdx.x;
    if (e < N_EDGES) {
        int p = atomicAdd(&g_fill[g_dst[e]], 1);
        g_srcbuf[clampN(p, N_EDGES)] = g_src[e];
    }
}

// ---------------- aggregation (fp16 gather): warp/node, half-warp/edge ----------------
// 4-deep gather batching: 8 edges per main-loop step (4 per half-warp), 4 independent
// LDG.64s in flight per half-warp -> MLP 4 (vs ~1), hiding L2 latency.
// COMBINE=false: g_aggx[n] = mean_{src} g_xh[src]                      (fp32 out)
// COMBINE=true : g_hh[n,0:64] = fp16(relu(mean g_yh[src] + bias + g_ys[n]))
template <bool COMBINE>
__global__ void k_aggh(const float* __restrict__ bias) {
    const __half* Yh = COMBINE ? g_yh : g_xh;
    int node = (blockIdx.x * blockDim.x + threadIdx.x) >> 5;
    if (node >= N_NODES) return;
    int lane = threadIdx.x & 31;
    int hw = lane >> 4, l16 = lane & 15;
    int p0 = g_ptr[node], p1 = g_ptr[node + 1];
    if (p1 > N_EDGES) p1 = N_EDGES;
    if (p0 < 0) p0 = 0;
    float ax = 0.f, ay = 0.f, az = 0.f, aw = 0.f;
    for (int base = p0; base < p1; base += 32) {
        int idx = base + lane;
        int s = (idx < p1) ? g_srcbuf[idx] : 0;
        int m = p1 - base;
        if (m > 32) m = 32;
        int j = 0;
        // main batches: 8 edges (4 per half-warp), all loads unconditional + independent
        for (; j + 8 <= m; j += 8) {
            int e0 = __shfl_sync(0xffffffffu, s, j + 0 + hw);
            int e1 = __shfl_sync(0xffffffffu, s, j + 2 + hw);
            int e2 = __shfl_sync(0xffffffffu, s, j + 4 + hw);
            int e3 = __shfl_sync(0xffffffffu, s, j + 6 + hw);
            uint2 u0 = *(const uint2*)(Yh + (size_t)e0 * 64 + l16 * 4);
            uint2 u1 = *(const uint2*)(Yh + (size_t)e1 * 64 + l16 * 4);
            uint2 u2 = *(const uint2*)(Yh + (size_t)e2 * 64 + l16 * 4);
            uint2 u3 = *(const uint2*)(Yh + (size_t)e3 * 64 + l16 * 4);
            float2 f0, f1;
            f0 = __half22float2(*(const __half2*)&u0.x);
            f1 = __half22float2(*(const __half2*)&u0.y);
            ax += f0.x; ay += f0.y; az += f1.x; aw += f1.y;
            f0 = __half22float2(*(const __half2*)&u1.x);
            f1 = __half22float2(*(const __half2*)&u1.y);
            ax += f0.x; ay += f0.y; az += f1.x; aw += f1.y;
            f0 = __half22float2(*(const __half2*)&u2.x);
            f1 = __half22float2(*(const __half2*)&u2.y);
            ax += f0.x; ay += f0.y; az += f1.x; aw += f1.y;
            f0 = __half22float2(*(const __half2*)&u3.x);
            f1 = __half22float2(*(const __half2*)&u3.y);
            ax += f0.x; ay += f0.y; az += f1.x; aw += f1.y;
        }
        // remainder: 2 edges per step
        for (; j < m; j += 2) {
            int ss = __shfl_sync(0xffffffffu, s, j + hw);
            if (j + hw < m) {
                uint2 u = *(const uint2*)(Yh + (size_t)ss * 64 + l16 * 4);
                float2 f0 = __half22float2(*(const __half2*)&u.x);
                float2 f1 = __half22float2(*(const __half2*)&u.y);
                ax += f0.x; ay += f0.y; az += f1.x; aw += f1.y;
            }
        }
    }
    ax += __shfl_xor_sync(0xffffffffu, ax, 16);
    ay += __shfl_xor_sync(0xffffffffu, ay, 16);
    az += __shfl_xor_sync(0xffffffffu, az, 16);
    aw += __shfl_xor_sync(0xffffffffu, aw, 16);
    float inv = g_deginv[node];
    ax *= inv; ay *= inv; az *= inv; aw *= inv;
    if (COMBINE) {
        float4 sv = ((const float4*)(g_ys + (size_t)node * 64))[l16];
        float4 bv = ((const float4*)bias)[l16];
        ax = fmaxf(ax + bv.x + sv.x, 0.f);
        ay = fmaxf(ay + bv.y + sv.y, 0.f);
        az = fmaxf(az + bv.z + sv.z, 0.f);
        aw = fmaxf(aw + bv.w + sv.w, 0.f);
        if (hw == 0) {
            __half2 h0 = __floats2half2_rn(ax, ay);
            __half2 h1 = __floats2half2_rn(az, aw);
            uint2 u;
            u.x = *(unsigned*)&h0;
            u.y = *(unsigned*)&h1;
            *(uint2*)(g_hh + (size_t)node * 64 + l16 * 4) = u;
        }
    } else if (hw == 0) {
        float4 o; o.x = ax; o.y = ay; o.z = az; o.w = aw;
        ((float4*)(g_aggx + (size_t)node * 64))[l16] = o;
    }
}

// ---------------- HMMA GEMM: C[128-tile, 128] = A @ Bt^T (mma.sync m16n8k16) --------
// fp16 A/B, fp32 accumulate. KT = 64 or 128 (64-K slabs in shared).
// ROWCAT: A = [g_aggx | x] fp32->fp16 on stage.  L1OUT: relu(+bias) -> g_hh[,128] fp16.
// else split: cols 0:64 (warpCol 0) -> g_yh fp16, cols 64:128 (warpCol 1) -> g_ys fp32.
#define SKH 72  // padded shared K-stride in halves (144 B rows: 16B-aligned, ldsm clean)
template <int KT, bool ROWCAT, bool L1OUT, int BTSEL>
__global__ void k_mma(const float* __restrict__ xExt, const float* __restrict__ bias) {
    __shared__ __half sA[128 * SKH];  // 18 KB
    __shared__ __half sB[128 * SKH];  // 18 KB
    __shared__ float sBias[128];
    int tid = threadIdx.x, wid = tid >> 5, lane = tid & 31;
    int warpRow = wid & 3, warpCol = wid >> 2;
    int row0 = blockIdx.x * 128;
    if (L1OUT && tid < 128) sBias[tid] = bias[tid];

    float acc[2][8][4];
    #pragma unroll
    for (int mt = 0; mt < 2; mt++)
        #pragma unroll
        for (int nt = 0; nt < 8; nt++)
            #pragma unroll
            for (int q = 0; q < 4; q++) acc[mt][nt][q] = 0.f;

    uint32_t aBase = s2u(sA), bBase = s2u(sB);
    int mi = lane >> 3, lr = lane & 7;
    uint32_t aAddr0 = aBase +
        (uint32_t)(((warpRow * 32 + (mi & 1) * 8 + lr) * SKH + (mi >> 1) * 8) * 2);
    uint32_t bAddr0 = bBase +
        (uint32_t)(((warpCol * 64 + (mi >> 1) * 8 + lr) * SKH + (mi & 1) * 8) * 2);
    const __half* Bt = btp<BTSEL>();

    for (int p = 0; p < KT / 64; p++) {
        int kc = p * 64;
        for (int t = tid; t < 1024; t += 256) {
            int r = t >> 3, q = (t & 7) * 8;
            int row = row0 + r;
            uint4 u = make_uint4(0, 0, 0, 0);
            if (row < N_NODES) {
                if (ROWCAT) {
                    const float* src = (p == 0) ? (g_aggx + (size_t)row * 64 + q)
                                                : (xExt + (size_t)row * 64 + q);
                    float4 f0 = *(const float4*)src;
                    float4 f1 = *(const float4*)(src + 4);
                    __half2 h0 = __floats2half2_rn(f0.x, f0.y);
                    __half2 h1 = __floats2half2_rn(f0.z, f0.w);
                    __half2 h2 = __floats2half2_rn(f1.x, f1.y);
                    __half2 h3 = __floats2half2_rn(f1.z, f1.w);
                    u.x = *(unsigned*)&h0; u.y = *(unsigned*)&h1;
                    u.z = *(unsigned*)&h2; u.w = *(unsigned*)&h3;
                } else {
                    u = *(const uint4*)(g_hh + (size_t)row * KT + kc + q);
                }
            }
            *(uint4*)(sA + r * SKH + q) = u;
        }
        for (int t = tid; t < 1024; t += 256) {
            int n = t >> 3, q = (t & 7) * 8;
            uint4 u = *(const uint4*)(Bt + n * KT + kc + q);
            *(uint4*)(sB + n * SKH + q) = u;
        }
        __syncthreads();

        #pragma unroll
        for (int ks = 0; ks < 4; ks++) {
            uint32_t koff = (uint32_t)(ks * 32);
            uint32_t b[4][4];
            #pragma unroll
            for (int nt2 = 0; nt2 < 4; nt2++)
                ldsm_x4(bAddr0 + (uint32_t)(nt2 * 16 * SKH * 2) + koff,
                        b[nt2][0], b[nt2][1], b[nt2][2], b[nt2][3]);
            #pragma unroll
            for (int mt = 0; mt < 2; mt++) {
                uint32_t a[4];
                ldsm_x4(aAddr0 + (uint32_t)(mt * 16 * SKH * 2) + koff,
                        a[0], a[1], a[2], a[3]);
                #pragma unroll
                for (int nt2 = 0; nt2 < 4; nt2++) {
                    mma16816(acc[mt][nt2 * 2 + 0], a, b[nt2][0], b[nt2][1]);
                    mma16816(acc[mt][nt2 * 2 + 1], a, b[nt2][2], b[nt2][3]);
                }
            }
        }
        __syncthreads();
    }

    int gr = lane >> 2, gc = lane & 3;
    #pragma unroll
    for (int mt = 0; mt < 2; mt++) {
        #pragma unroll
        for (int h = 0; h < 2; h++) {
            int row = row0 + warpRow * 32 + mt * 16 + gr + h * 8;
            if (row < N_NODES) {
                #pragma unroll
                for (int nt = 0; nt < 8; nt++) {
                    int col = warpCol * 64 + nt * 8 + 2 * gc;
                    float v0 = acc[mt][nt][h * 2 + 0];
                    float v1 = acc[mt][nt][h * 2 + 1];
                    if (L1OUT) {
                        v0 = fmaxf(v0 + sBias[col], 0.f);
                        v1 = fmaxf(v1 + sBias[col + 1], 0.f);
                        __half2 hv = __floats2half2_rn(v0, v1);
                        *(unsigned*)(g_hh + (size_t)row * 128 + col) = *(unsigned*)&hv;
                    } else if (warpCol == 0) {
                        __half2 hv = __floats2half2_rn(v0, v1);
                        *(unsigned*)(g_yh + (size_t)row * 64 + col) = *(unsigned*)&hv;
                    } else {
                        float2 fv = make_float2(v0, v1);
                        *(float2*)(g_ys + (size_t)row * 64 + (col - 64)) = fv;
                    }
                }
            }
        }
    }
}

// ---------------- global mean pool (batch sorted -> contiguous segments) ----------------
__global__ void k_pool() {
    int g = blockIdx.x;
    int c = threadIdx.x;
    int r0 = g_gptr[g], r1 = g_gptr[g + 1];
    if (r1 > N_NODES) r1 = N_NODES;
    if (r0 < 0) r0 = 0;
    float acc = 0.f;
    for (int r = r0; r < r1; r++) acc += __half2float(g_hh[(size_t)r * 64 + c]);
    int cnt = r1 - r0;
    g_pool[g * 64 + c] = acc / (float)(cnt > 0 ? cnt : 1);
}

// ---------------- MLP head: 1024 rows, one thread per row ----------------
__global__ void k_mlp(const float* __restrict__ w1, const float* __restrict__ b1,
                      const float* __restrict__ w2, const float* __restrict__ b2,
                      const float* __restrict__ w3, const float* __restrict__ b3,
                      const float* __restrict__ w4, const float* __restrict__ b4,
                      float* __restrict__ out) {
    __shared__ float s1[64 * 64], sb1[64], s2[64 * 32], sb2[32], s3[32 * 32], sb3[32], s4[32];
    __shared__ float sb4;
    int tid = threadIdx.x;
    for (int i = tid; i < 4096; i += 256) s1[i] = w1[i];
    for (int i = tid; i < 2048; i += 256) s2[i] = w2[i];
    for (int i = tid; i < 1024; i += 256) s3[i] = w3[i];
    if (tid < 64) sb1[tid] = b1[tid];
    if (tid < 32) { sb2[tid] = b2[tid]; sb3[tid] = b3[tid]; s4[tid] = w4[tid]; }
    if (tid == 0) sb4 = b4[0];
    __syncthreads();
    int row = blockIdx.x * 256 + tid;
    if (row >= N_GRAPHS) return;
    float gin[64];
    #pragma unroll
    for (int k = 0; k < 64; k++) gin[k] = g_pool[row * 64 + k];
    float h1[64];
    for (int j = 0; j < 64; j++) {
        float a = sb1[j];
        #pragma unroll
        for (int k = 0; k < 64; k++) a += gin[k] * s1[k * 64 + j];
        h1[j] = fmaxf(a, 0.f);
    }
    float h2[32];
    for (int j = 0; j < 32; j++) {
        float a = sb2[j];
        #pragma unroll
        for (int k = 0; k < 64; k++) a += h1[k] * s2[k * 32 + j];
        h2[j] = fmaxf(a, 0.f);
    }
    float h3[32];
    for (int j = 0; j < 32; j++) {
        float a = sb3[j];
        #pragma unroll
        for (int k = 0; k < 32; k++) a += h2[k] * s3[k * 32 + j];
        h3[j] = fmaxf(a, 0.f);
    }
    float o = sb4;
    #pragma unroll
    for (int k = 0; k < 32; k++) o += h3[k] * s4[k];
    out[row] = o;
}

// ---------------- host launch: KERNEL LAUNCHES ONLY ----------------
extern "C" void kernel_launch(void* const* d_in, const int* in_sizes, int n_in,
                              void* d_out, int out_size) {
    const float* x = (const float*)d_in[0];
    const void* ei = d_in[1];
    const void* batch = d_in[2];
    const float* c1wl = (const float*)d_in[3];
    const float* c1bl = (const float*)d_in[4];
    const float* c1wr = (const float*)d_in[5];
    const float* c2wl = (const float*)d_in[6];
    const float* c2bl = (const float*)d_in[7];
    const float* c2wr = (const float*)d_in[8];
    const float* c3wl = (const float*)d_in[9];
    const float* c3bl = (const float*)d_in[10];
    const float* c3wr = (const float*)d_in[11];
    const float* c4wl = (const float*)d_in[12];
    const float* c4bl = (const float*)d_in[13];
    const float* c4wr = (const float*)d_in[14];
    const float* l1w = (const float*)d_in[15];
    const float* l1b = (const float*)d_in[16];
    const float* l2w = (const float*)d_in[17];
    const float* l2b = (const float*)d_in[18];
    const float* l3w = (const float*)d_in[19];
    const float* l3b = (const float*)d_in[20];
    const float* l4w = (const float*)d_in[21];
    const float* l4b = (const float*)d_in[22];
    float* out = (float*)d_out;

    int aggBlocks = (N_NODES * 32 + 255) / 256;
    int mmaBlocks = (N_NODES + 127) / 128;

    k_zero<<<(N_NODES + 255) / 256, 256>>>((const unsigned int*)ei,
        c1wl, c1wr, c2wl, c2wr, c3wl, c3wr, c4wl, c4wr);
    k_cvt<<<(N_EDGES + 255) / 256, 256>>>(ei, batch, x);
    k_scanA<<<SCAN_BLOCKS, 1024>>>();
    k_scanB<<<1, 1024>>>();
    k_scanC<<<(N_NODES + 1023) / 1024, 1024>>>();
    k_fill<<<(N_EDGES + 255) / 256, 256>>>();

    // layer 1: aggx = mean(xh[src]); h1 = relu([aggx|x] @ [wl;wr] + b1) -> g_hh[,128] fp16
    k_aggh<false><<<aggBlocks, 256>>>(nullptr);
    k_mma<128, true, true, 1><<<mmaBlocks, 256>>>(x, c1bl);

    // layer 2: y = h1 @ [wl|wr] split; h2 = relu(mean(yh[src]) + b2 + ys) -> g_hh[,64] fp16
    k_mma<128, false, false, 2><<<mmaBlocks, 256>>>(nullptr, nullptr);
    k_aggh<true><<<aggBlocks, 256>>>(c2bl);

    // layer 3
    k_mma<64, false, false, 3><<<mmaBlocks, 256>>>(nullptr, nullptr);
    k_aggh<true><<<aggBlocks, 256>>>(c3bl);

    // layer 4
    k_mma<64, false, false, 4><<<mmaBlocks, 256>>>(nullptr, nullptr);
    k_aggh<true><<<aggBlocks, 256>>>(c4bl);

    // pool + MLP head
    k_pool<<<N_GRAPHS, 64>>>();
    k_mlp<<<(N_GRAPHS + 255) / 256, 256>>>(l1w, l1b, l2w, l2b, l3w, l3b, l4w, l4b, out);
}